// round 13
// baseline (speedup 1.0000x reference)
#include <cuda_runtime.h>
#include <cstdint>

// CapsuleLayer: x[8,2048,512], W[32,512,64] -> nodes[8,32,64]
// Fused routing, capsules never materialized:
//   nodes = (sum_s r*x) @ W[n];  agreement = x . (W[n] @ tanh(nodes))

#define BB 8
#define SS 2048
#define II 512
#define NN 32
#define DD 64
#define TS 32            // s-rows per sub-tile
#define NSUB 4           // sub-tiles per fused block
#define NT2 16           // fused blocks per b
#define PP 32            // xsum partial slabs
#define BNI (BB*NN*II)   // 131072

typedef unsigned long long ull;

__device__ __align__(16) float g_xsumP[PP*BB*II];
__device__ __align__(16) float g_yP[NT2*BNI];   // slab-major y partials (8MB)
__device__ __align__(16) float g_y[BNI];        // reduced y (0.5MB)
__device__ __align__(16) float g_U[BB*II*NN];   // [b][i>>2][n][i&3]
__device__ float g_b1[BB*SS*NN];

__device__ __forceinline__ void ffma2(ull &d, ull a, ull b){
    asm("fma.rn.f32x2 %0, %1, %2, %0;" : "+l"(d) : "l"(a), "l"(b));
}
__device__ __forceinline__ ull pack2(float lo, float hi){
    ull r; asm("mov.b64 %0, {%1, %2};" : "=l"(r) : "f"(lo), "f"(hi)); return r;
}
__device__ __forceinline__ float2 unpack2(ull v){
    float2 r; asm("mov.b64 {%0, %1}, %2;" : "=f"(r.x), "=f"(r.y) : "l"(v)); return r;
}
__device__ __forceinline__ void cpasync16(uint32_t saddr, const void* g){
    asm volatile("cp.async.cg.shared.global [%0], [%1], 16;" :: "r"(saddr), "l"(g));
}

// ------------------------------------------------ xsum partials (no atomics)
__global__ void xsum_kernel(const float* __restrict__ x){
    int p = blockIdx.x, b = blockIdx.y, tid = threadIdx.x;   // grid (PP,8), 512 thr
    const float* xp = x + ((size_t)(b*SS + p*(SS/PP)))*II + tid;
    float acc = 0.f;
    #pragma unroll 16
    for (int r = 0; r < SS/PP; r++) acc += xp[(size_t)r*II];
    g_xsumP[(size_t)(p*BB + b)*II + tid] = acc;
}

// ------------------------------------------------ yP -> y, single stage
// grid 256 x 256 thr; one float2 per thread, 16 slabs, MLP 16.
__global__ void reduce_y_kernel(){
    int idx = blockIdx.x*256 + threadIdx.x;      // [0, BNI/2)
    const float2* src = ((const float2*)g_yP) + idx;
    float2 a = {0.f, 0.f};
    #pragma unroll
    for (int t = 0; t < NT2; t++){
        float2 v = src[(size_t)t*(BNI/2)];
        a.x += v.x; a.y += v.y;
    }
    ((float2*)g_y)[idx] = a;
}

// ------------------------------------------------ nodes / tanh / U, 4 batches per block
// grid (NN, 2), 512 threads; one W[n] stream serves 4 batches.
__global__ void __launch_bounds__(512)
nodes_update_kernel(const float* __restrict__ W, float scale,
                    int use_xsum, float* __restrict__ out){
    int n = blockIdx.x, bg = blockIdx.y, tid = threadIdx.x;
    __shared__ float ys[4][II];
    __shared__ float sPart[4][32*68];   // padded stride 68
    __shared__ float tsm[4][DD];

    if (tid < II){
        #pragma unroll
        for (int bb = 0; bb < 4; bb++){
            int b = bg*4 + bb;
            float a;
            if (use_xsum){
                a = 0.f;
                const float* p0 = g_xsumP + tid;
                #pragma unroll 16
                for (int p = 0; p < PP; p++) a += p0[(size_t)(p*BB + b)*II];
            } else {
                a = g_y[(size_t)(b*NN + n)*II + tid];
            }
            ys[bb][tid] = a;
        }
    }
    __syncthreads();

    // part A: nd[b][d] = sum_i ys[b][i]*W[n][i][d]
    {
        int d4 = tid & 15, ch = tid >> 4;
        const float4* Wp = (const float4*)(W + ((size_t)n*II + ch*16)*DD) + d4;
        float4 a0 = {0,0,0,0}, a1 = {0,0,0,0}, a2 = {0,0,0,0}, a3 = {0,0,0,0};
        #pragma unroll
        for (int j = 0; j < 16; j++){
            float4 w = Wp[j*16];
            float y0 = ys[0][ch*16+j], y1 = ys[1][ch*16+j];
            float y2 = ys[2][ch*16+j], y3 = ys[3][ch*16+j];
            a0.x += y0*w.x; a0.y += y0*w.y; a0.z += y0*w.z; a0.w += y0*w.w;
            a1.x += y1*w.x; a1.y += y1*w.y; a1.z += y1*w.z; a1.w += y1*w.w;
            a2.x += y2*w.x; a2.y += y2*w.y; a2.z += y2*w.z; a2.w += y2*w.w;
            a3.x += y3*w.x; a3.y += y3*w.y; a3.z += y3*w.z; a3.w += y3*w.w;
        }
        float* s0 = &sPart[0][ch*68 + d4*4];
        float* s1 = &sPart[1][ch*68 + d4*4];
        float* s2 = &sPart[2][ch*68 + d4*4];
        float* s3 = &sPart[3][ch*68 + d4*4];
        s0[0]=a0.x; s0[1]=a0.y; s0[2]=a0.z; s0[3]=a0.w;
        s1[0]=a1.x; s1[1]=a1.y; s1[2]=a1.z; s1[3]=a1.w;
        s2[0]=a2.x; s2[1]=a2.y; s2[2]=a2.z; s2[3]=a2.w;
        s3[0]=a3.x; s3[1]=a3.y; s3[2]=a3.z; s3[3]=a3.w;
    }
    __syncthreads();
    if (tid < 256){
        int bb = tid >> 6, d = tid & 63;
        float nd = 0.f;
        #pragma unroll
        for (int ch = 0; ch < 32; ch++) nd += sPart[bb][ch*68 + d];
        nd *= scale;
        if (out) out[(size_t)((bg*4+bb)*NN + n)*DD + d] = nd;
        else     tsm[bb][d] = tanhf(nd);
    }
    __syncthreads();

    // part B: U[b,n,i] = W[n][i][:] . tanh(nd[b])
    if (!out){
        int i = tid;
        const float4* Wr = (const float4*)(W + ((size_t)n*II + i)*DD);
        float u0 = 0.f, u1 = 0.f, u2 = 0.f, u3 = 0.f;
        #pragma unroll
        for (int d4 = 0; d4 < 16; d4++){
            float4 w = Wr[d4];
            u0 += w.x*tsm[0][4*d4] + w.y*tsm[0][4*d4+1] + w.z*tsm[0][4*d4+2] + w.w*tsm[0][4*d4+3];
            u1 += w.x*tsm[1][4*d4] + w.y*tsm[1][4*d4+1] + w.z*tsm[1][4*d4+2] + w.w*tsm[1][4*d4+3];
            u2 += w.x*tsm[2][4*d4] + w.y*tsm[2][4*d4+1] + w.z*tsm[2][4*d4+2] + w.w*tsm[2][4*d4+3];
            u3 += w.x*tsm[3][4*d4] + w.y*tsm[3][4*d4+1] + w.z*tsm[3][4*d4+2] + w.w*tsm[3][4*d4+3];
        }
        size_t off = (size_t)(i>>2)*(NN*4) + n*4 + (i&3);
        g_U[(size_t)(bg*4+0)*(II*NN) + off] = u0;
        g_U[(size_t)(bg*4+1)*(II*NN) + off] = u1;
        g_U[(size_t)(bg*4+2)*(II*NN) + off] = u2;
        g_U[(size_t)(bg*4+3)*(II*NN) + off] = u3;
    }
}

// ------------------------------------------------ fused routing pass
// 4 sub-tiles of 32 rows, double-buffered cp.async x staging.
// grid (NT2, BB), 512 threads, 224KB dynamic smem.
__global__ void __launch_bounds__(512, 1)
fused_pass_kernel(const float* __restrict__ x, int pass_c){
    extern __shared__ float smem[];
    float* sXb[2] = { smem, smem + TS*II };      // 2 x 16384 floats
    float* sU = smem + 2*TS*II;                  // 16384 floats (quad layout)
    float* sP = sU + II*NN;                      // 8*TS*NN = 8192 floats
    float* sR = sP;                              // aliases sP (barrier-guarded)
    int blk = blockIdx.x, b = blockIdx.y, tid = threadIdx.x;
    int warp = tid >> 5, lane = tid & 31;

    // ---- stage U (normal loads; visible after first __syncthreads)
    const float* Ub = g_U + (size_t)b*(II*NN);
    #pragma unroll
    for (int it = 0; it < II*NN/4/512; it++)
        ((float4*)sU)[it*512 + tid] = ((const float4*)Ub)[it*512 + tid];

    // ---- cp.async staging helper state
    uint32_t sXaddr[2] = { (uint32_t)__cvta_generic_to_shared(sXb[0]),
                           (uint32_t)__cvta_generic_to_shared(sXb[1]) };

    // prologue: issue sub-tile 0
    {
        const float4* xt = (const float4*)(x + ((size_t)(b*SS + blk*NSUB*TS))*II);
        uint32_t dst = sXaddr[0] + tid*16;
        #pragma unroll
        for (int it = 0; it < TS*II/4/512; it++)
            cpasync16(dst + it*512*16, xt + it*512 + tid);
        asm volatile("cp.async.commit_group;");
    }

    // phase-2 persistent accumulators: thread -> 8 n x 4 i-floats
    int g2 = tid >> 7, c = tid & 127, nb = g2*8;
    ull acc[16];
    #pragma unroll
    for (int p = 0; p < 16; p++) acc[p] = 0ULL;

    #pragma unroll 1
    for (int st = 0; st < NSUB; st++){
        // issue next sub-tile into the other buffer
        if (st + 1 < NSUB){
            const float4* xt = (const float4*)(x + ((size_t)(b*SS + (blk*NSUB + st + 1)*TS))*II);
            uint32_t dst = sXaddr[(st+1)&1] + tid*16;
            #pragma unroll
            for (int it = 0; it < TS*II/4/512; it++)
                cpasync16(dst + it*512*16, xt + it*512 + tid);
            asm volatile("cp.async.commit_group;");
            asm volatile("cp.async.wait_group 1;");
        } else {
            asm volatile("cp.async.wait_group 0;");
        }
        __syncthreads();

        float* sX = sXb[st&1];
        int s0 = (blk*NSUB + st)*TS;

        // ---- phase 1a: agreement; warp = (rg rows of 16, ks K-slice of 16 quads)
        {
            int rg = warp >> 3, ks = warp & 7;
            int row0 = rg*16, q0 = ks*16;
            ull a2[16];
            #pragma unroll
            for (int r = 0; r < 16; r++) a2[r] = 0ULL;
            const ulonglong2* U2 = (const ulonglong2*)sU;   // [q*NN + n] -> 4 floats
            #pragma unroll 2
            for (int qq = 0; qq < 16; qq++){
                int q = q0 + qq;
                ulonglong2 u = U2[q*NN + lane];
                #pragma unroll
                for (int rr = 0; rr < 16; rr++){
                    const ulonglong2 xv = *(const ulonglong2*)&sX[(row0+rr)*II + q*4];
                    ffma2(a2[rr], xv.x, u.x);
                    ffma2(a2[rr], xv.y, u.y);
                }
            }
            #pragma unroll
            for (int rr = 0; rr < 16; rr++){
                float2 p = unpack2(a2[rr]);
                sP[ks*(TS*NN) + (row0+rr)*NN + lane] = p.x + p.y;
            }
        }
        __syncthreads();

        // ---- phase 1b: combine 8 K-splits + softmax; each warp 2 rows, lane = n
        {
            int row0 = warp*2;
            float rv[2];
            #pragma unroll
            for (int rr = 0; rr < 2; rr++){
                int row = row0 + rr;
                float a = 0.f;
                #pragma unroll
                for (int k = 0; k < 8; k++) a += sP[k*(TS*NN) + row*NN + lane];
                int gidx = ((b*SS) + s0 + row)*NN + lane;
                if (pass_c) a += g_b1[gidx];
                else        g_b1[gidx] = a;
                float m = a;
                #pragma unroll
                for (int off = 16; off > 0; off >>= 1)
                    m = fmaxf(m, __shfl_xor_sync(0xffffffffu, m, off));
                float e = __expf(a - m);
                float ssum = e;
                #pragma unroll
                for (int off = 16; off > 0; off >>= 1)
                    ssum += __shfl_xor_sync(0xffffffffu, ssum, off);
                rv[rr] = e / ssum;
            }
            __syncthreads();             // all sP reads done before aliasing writes
            #pragma unroll
            for (int rr = 0; rr < 2; rr++)
                sR[(row0+rr)*NN + lane] = rv[rr];
        }
        __syncthreads();

        // ---- phase 2: acc += r^T x over this sub-tile
        for (int ts = 0; ts < TS; ts++){
            const ulonglong2 rA = *(const ulonglong2*)&sR[ts*NN + nb];
            const ulonglong2 rB = *(const ulonglong2*)&sR[ts*NN + nb + 4];
            float2 r01 = unpack2(rA.x), r23 = unpack2(rA.y);
            float2 r45 = unpack2(rB.x), r67 = unpack2(rB.y);
            ull rv0 = pack2(r01.x, r01.x), rv1 = pack2(r01.y, r01.y);
            ull rv2 = pack2(r23.x, r23.x), rv3 = pack2(r23.y, r23.y);
            ull rv4 = pack2(r45.x, r45.x), rv5 = pack2(r45.y, r45.y);
            ull rv6 = pack2(r67.x, r67.x), rv7 = pack2(r67.y, r67.y);
            const ulonglong2 xv = *(const ulonglong2*)&sX[ts*II + c*4];
            ffma2(acc[0],  xv.x, rv0); ffma2(acc[1],  xv.y, rv0);
            ffma2(acc[2],  xv.x, rv1); ffma2(acc[3],  xv.y, rv1);
            ffma2(acc[4],  xv.x, rv2); ffma2(acc[5],  xv.y, rv2);
            ffma2(acc[6],  xv.x, rv3); ffma2(acc[7],  xv.y, rv3);
            ffma2(acc[8],  xv.x, rv4); ffma2(acc[9],  xv.y, rv4);
            ffma2(acc[10], xv.x, rv5); ffma2(acc[11], xv.y, rv5);
            ffma2(acc[12], xv.x, rv6); ffma2(acc[13], xv.y, rv6);
            ffma2(acc[14], xv.x, rv7); ffma2(acc[15], xv.y, rv7);
        }
        __syncthreads();   // compute done reading sX/sR before next iteration
    }

    // ---- flush per-block y partials (slab-major, coalesced STG.128)
    float* dst = g_yP + (size_t)blk*BNI;
    #pragma unroll
    for (int j = 0; j < 8; j++){
        float2 p0 = unpack2(acc[2*j]);
        float2 p1 = unpack2(acc[2*j+1]);
        float4 v = {p0.x, p0.y, p1.x, p1.y};
        *(float4*)&dst[(size_t)(b*NN + nb + j)*II + c*4] = v;
    }
}

// ------------------------------------------------ launch (8 kernels)
extern "C" void kernel_launch(void* const* d_in, const int* in_sizes, int n_in,
                              void* d_out, int out_size){
    const float* x = (const float*)d_in[0];
    const float* W = (const float*)d_in[1];
    float* out = (float*)d_out;

    const size_t shmem = (size_t)(2*TS*II + II*NN + 8*TS*NN) * sizeof(float); // 229376
    cudaFuncSetAttribute(fused_pass_kernel,
                         cudaFuncAttributeMaxDynamicSharedMemorySize, (int)shmem);

    // it 0: r uniform -> nodes0 from xsum
    xsum_kernel<<<dim3(PP, BB), 512>>>(x);
    nodes_update_kernel<<<dim3(NN, 2), 512>>>(W, 1.0f/32.0f, 1, nullptr);

    // it 1
    fused_pass_kernel<<<dim3(NT2, BB), 512, shmem>>>(x, 0);
    reduce_y_kernel<<<256, 256>>>();
    nodes_update_kernel<<<dim3(NN, 2), 512>>>(W, 1.0f, 0, nullptr);

    // it 2
    fused_pass_kernel<<<dim3(NT2, BB), 512, shmem>>>(x, 1);
    reduce_y_kernel<<<256, 256>>>();
    nodes_update_kernel<<<dim3(NN, 2), 512>>>(W, 1.0f, 0, out);
}

// round 14
// speedup vs baseline: 1.3190x; 1.3190x over previous
#include <cuda_runtime.h>

// CapsuleLayer: x[8,2048,512], W[32,512,64] -> nodes[8,32,64]
// Fused routing, capsules never materialized:
//   nodes = (sum_s r*x) @ W[n];  agreement = x . (W[n] @ tanh(nodes))

#define BB 8
#define SS 2048
#define II 512
#define NN 32
#define DD 64
#define TS 64            // s-rows per sub-tile
#define NT2 16           // fused blocks per b (2 sub-tiles each)
#define PP 32            // xsum partial slabs
#define BNI (BB*NN*II)   // 131072

typedef unsigned long long ull;

__device__ __align__(16) float g_xsumP[PP*BB*II];
__device__ __align__(16) float g_yP[NT2*BNI];   // slab-major y partials (8MB)
__device__ __align__(16) float g_y[BNI];        // reduced y (0.5MB)
__device__ __align__(16) float g_U[BB*II*NN];   // [b][i>>2][n][i&3]
__device__ float g_b1[BB*SS*NN];

__device__ __forceinline__ void ffma2(ull &d, ull a, ull b){
    asm("fma.rn.f32x2 %0, %1, %2, %0;" : "+l"(d) : "l"(a), "l"(b));
}
__device__ __forceinline__ ull pack2(float lo, float hi){
    ull r; asm("mov.b64 %0, {%1, %2};" : "=l"(r) : "f"(lo), "f"(hi)); return r;
}
__device__ __forceinline__ float2 unpack2(ull v){
    float2 r; asm("mov.b64 {%0, %1}, %2;" : "=f"(r.x), "=f"(r.y) : "l"(v)); return r;
}

// ------------------------------------------------ xsum partials (no atomics)
// grid (PP,8), 512 thr; 64 rows per slab, MLP 16.
__global__ void xsum_kernel(const float* __restrict__ x){
    int p = blockIdx.x, b = blockIdx.y, tid = threadIdx.x;
    const float* xp = x + ((size_t)(b*SS + p*(SS/PP)))*II + tid;
    float acc = 0.f;
    #pragma unroll 16
    for (int r = 0; r < SS/PP; r++) acc += xp[(size_t)r*II];
    g_xsumP[(size_t)(p*BB + b)*II + tid] = acc;
}

// ------------------------------------------------ yP -> y, single stage
// grid 256 x 256 thr; one float2 per thread, reduces 16 slabs, MLP 16.
__global__ void reduce_y_kernel(){
    int idx = blockIdx.x*256 + threadIdx.x;      // [0, BNI/2) float2 index
    const float2* src = ((const float2*)g_yP) + idx;
    float2 a = {0.f, 0.f};
    #pragma unroll
    for (int t = 0; t < NT2; t++){
        float2 v = src[(size_t)t*(BNI/2)];
        a.x += v.x; a.y += v.y;
    }
    ((float2*)g_y)[idx] = a;
}

// ------------------------------------------------ nodes / tanh / U, 4 batches per block
// grid (NN, 2), 512 threads; block = (n, batch-group of 4). One W[n] stream serves 4 b.
__global__ void __launch_bounds__(512)
nodes_update_kernel(const float* __restrict__ W, float scale,
                    int use_xsum, float* __restrict__ out){
    int n = blockIdx.x, bg = blockIdx.y, tid = threadIdx.x;
    __shared__ float ys[4][II];
    __shared__ float sPart[4][32*68];   // padded stride 68
    __shared__ float tsm[4][DD];

    // ---- load ys for 4 batches
    if (tid < II){
        #pragma unroll
        for (int bb = 0; bb < 4; bb++){
            int b = bg*4 + bb;
            float a;
            if (use_xsum){
                a = 0.f;
                const float* p0 = g_xsumP + tid;
                #pragma unroll
                for (int p = 0; p < PP; p++) a += p0[(size_t)(p*BB + b)*II];
            } else {
                a = g_y[(size_t)(b*NN + n)*II + tid];
            }
            ys[bb][tid] = a;
        }
    }
    __syncthreads();

    // ---- part A: nd[b][d] = sum_i ys[b][i]*W[n][i][d]; W quad loaded once per 4 b
    {
        int d4 = tid & 15, ch = tid >> 4;           // 16 d-quads x 32 i-chunks
        const float4* Wp = (const float4*)(W + ((size_t)n*II + ch*16)*DD) + d4;
        float4 a0 = {0,0,0,0}, a1 = {0,0,0,0}, a2 = {0,0,0,0}, a3 = {0,0,0,0};
        #pragma unroll
        for (int j = 0; j < 16; j++){
            float4 w = Wp[j*16];
            float y0 = ys[0][ch*16+j], y1 = ys[1][ch*16+j];
            float y2 = ys[2][ch*16+j], y3 = ys[3][ch*16+j];
            a0.x += y0*w.x; a0.y += y0*w.y; a0.z += y0*w.z; a0.w += y0*w.w;
            a1.x += y1*w.x; a1.y += y1*w.y; a1.z += y1*w.z; a1.w += y1*w.w;
            a2.x += y2*w.x; a2.y += y2*w.y; a2.z += y2*w.z; a2.w += y2*w.w;
            a3.x += y3*w.x; a3.y += y3*w.y; a3.z += y3*w.z; a3.w += y3*w.w;
        }
        float* s0 = &sPart[0][ch*68 + d4*4];
        float* s1 = &sPart[1][ch*68 + d4*4];
        float* s2 = &sPart[2][ch*68 + d4*4];
        float* s3 = &sPart[3][ch*68 + d4*4];
        s0[0]=a0.x; s0[1]=a0.y; s0[2]=a0.z; s0[3]=a0.w;
        s1[0]=a1.x; s1[1]=a1.y; s1[2]=a1.z; s1[3]=a1.w;
        s2[0]=a2.x; s2[1]=a2.y; s2[2]=a2.z; s2[3]=a2.w;
        s3[0]=a3.x; s3[1]=a3.y; s3[2]=a3.z; s3[3]=a3.w;
    }
    __syncthreads();
    if (tid < 256){
        int bb = tid >> 6, d = tid & 63;
        float nd = 0.f;
        #pragma unroll
        for (int ch = 0; ch < 32; ch++) nd += sPart[bb][ch*68 + d];
        nd *= scale;
        if (out) out[(size_t)((bg*4+bb)*NN + n)*DD + d] = nd;
        else     tsm[bb][d] = tanhf(nd);
    }
    __syncthreads();

    // ---- part B: U[b,n,i] = W[n][i][:] . tanh(nd[b]); one i per thread, 4 b per W row
    if (!out){
        int i = tid;
        const float4* Wr = (const float4*)(W + ((size_t)n*II + i)*DD);
        float u0 = 0.f, u1 = 0.f, u2 = 0.f, u3 = 0.f;
        #pragma unroll
        for (int d4 = 0; d4 < 16; d4++){
            float4 w = Wr[d4];
            u0 += w.x*tsm[0][4*d4] + w.y*tsm[0][4*d4+1] + w.z*tsm[0][4*d4+2] + w.w*tsm[0][4*d4+3];
            u1 += w.x*tsm[1][4*d4] + w.y*tsm[1][4*d4+1] + w.z*tsm[1][4*d4+2] + w.w*tsm[1][4*d4+3];
            u2 += w.x*tsm[2][4*d4] + w.y*tsm[2][4*d4+1] + w.z*tsm[2][4*d4+2] + w.w*tsm[2][4*d4+3];
            u3 += w.x*tsm[3][4*d4] + w.y*tsm[3][4*d4+1] + w.z*tsm[3][4*d4+2] + w.w*tsm[3][4*d4+3];
        }
        size_t off = (size_t)(i>>2)*(NN*4) + n*4 + (i&3);
        g_U[(size_t)(bg*4+0)*(II*NN) + off] = u0;
        g_U[(size_t)(bg*4+1)*(II*NN) + off] = u1;
        g_U[(size_t)(bg*4+2)*(II*NN) + off] = u2;
        g_U[(size_t)(bg*4+3)*(II*NN) + off] = u3;
    }
}

// ------------------------------------------------ fused routing pass (2 sub-tiles/block)
// a[n] = x.U[n] (+b_prev) -> softmax_n -> acc += r^T x; flush once to yP[blk].
// grid (NT2, BB), 512 threads, 224KB dynamic smem.
__global__ void __launch_bounds__(512, 1)
fused_pass_kernel(const float* __restrict__ x, int pass_c){
    extern __shared__ float smem[];
    float* sX = smem;             // TS*II  = 32768 floats (128KB)
    float* sU = sX + TS*II;       // II*NN  = 16384 floats (64KB, quad layout)
    float* sP = sU + II*NN;       // 4*TS*NN = 8192 floats (32KB, K-split partials)
    float* sR = sP;               // aliases sP (guarded by barriers)
    int blk = blockIdx.x, b = blockIdx.y, tid = threadIdx.x;
    int warp = tid >> 5, lane = tid & 31;

    // ---- stage U once
    const float* Ub = g_U + (size_t)b*(II*NN);
    #pragma unroll
    for (int it = 0; it < II*NN/4/512; it++)
        ((float4*)sU)[it*512 + tid] = ((const float4*)Ub)[it*512 + tid];

    // phase-2 persistent accumulators: thread -> 8 n x 4 i-floats
    int g2 = tid >> 7, c = tid & 127, nb = g2*8;
    ull acc[16];
    #pragma unroll
    for (int p = 0; p < 16; p++) acc[p] = 0ULL;

    #pragma unroll 1
    for (int st = 0; st < 2; st++){
        int s0 = (blk*2 + st)*TS;

        // ---- stage x sub-tile (coalesced float4)
        const float* xt = x + ((size_t)(b*SS + s0))*II;
        #pragma unroll
        for (int it = 0; it < TS*II/4/512; it++)
            ((float4*)sX)[it*512 + tid] = ((const float4*)xt)[it*512 + tid];
        __syncthreads();

        // ---- phase 1a: agreement; warp = (rg rows of 16, ks K-slice of 32 quads)
        {
            int rg = warp >> 2, ks = warp & 3;
            int row0 = rg*16, q0 = ks*32;
            ull a2[16];
            #pragma unroll
            for (int r = 0; r < 16; r++) a2[r] = 0ULL;
            const ulonglong2* U2 = (const ulonglong2*)sU;   // [q*NN + n] -> 4 floats
            #pragma unroll 2
            for (int qq = 0; qq < 32; qq++){
                int q = q0 + qq;
                ulonglong2 u = U2[q*NN + lane];
                #pragma unroll
                for (int rr = 0; rr < 16; rr++){
                    const ulonglong2 xv = *(const ulonglong2*)&sX[(row0+rr)*II + q*4];
                    ffma2(a2[rr], xv.x, u.x);
                    ffma2(a2[rr], xv.y, u.y);
                }
            }
            #pragma unroll
            for (int rr = 0; rr < 16; rr++){
                float2 p = unpack2(a2[rr]);
                sP[ks*(TS*NN) + (row0+rr)*NN + lane] = p.x + p.y;
            }
        }
        __syncthreads();

        // ---- phase 1b: combine 4 K-splits + softmax; each warp 4 rows, lane = n
        {
            int row0 = warp*4;
            float rv[4];
            #pragma unroll
            for (int rr = 0; rr < 4; rr++){
                int row = row0 + rr;
                float a = sP[row*NN + lane]
                        + sP[TS*NN + row*NN + lane]
                        + sP[2*TS*NN + row*NN + lane]
                        + sP[3*TS*NN + row*NN + lane];
                int gidx = ((b*SS) + s0 + row)*NN + lane;
                if (pass_c) a += g_b1[gidx];
                else        g_b1[gidx] = a;
                float m = a;
                #pragma unroll
                for (int off = 16; off > 0; off >>= 1)
                    m = fmaxf(m, __shfl_xor_sync(0xffffffffu, m, off));
                float e = __expf(a - m);
                float ssum = e;
                #pragma unroll
                for (int off = 16; off > 0; off >>= 1)
                    ssum += __shfl_xor_sync(0xffffffffu, ssum, off);
                rv[rr] = e / ssum;
            }
            __syncthreads();             // all sP reads done before aliasing writes
            #pragma unroll
            for (int rr = 0; rr < 4; rr++)
                sR[(row0+rr)*NN + lane] = rv[rr];
        }
        __syncthreads();

        // ---- phase 2: acc += r^T x over this sub-tile
        for (int ts = 0; ts < TS; ts++){
            const ulonglong2 rA = *(const ulonglong2*)&sR[ts*NN + nb];
            const ulonglong2 rB = *(const ulonglong2*)&sR[ts*NN + nb + 4];
            float2 r01 = unpack2(rA.x), r23 = unpack2(rA.y);
            float2 r45 = unpack2(rB.x), r67 = unpack2(rB.y);
            ull rv0 = pack2(r01.x, r01.x), rv1 = pack2(r01.y, r01.y);
            ull rv2 = pack2(r23.x, r23.x), rv3 = pack2(r23.y, r23.y);
            ull rv4 = pack2(r45.x, r45.x), rv5 = pack2(r45.y, r45.y);
            ull rv6 = pack2(r67.x, r67.x), rv7 = pack2(r67.y, r67.y);
            const ulonglong2 xv = *(const ulonglong2*)&sX[ts*II + c*4];
            ffma2(acc[0],  xv.x, rv0); ffma2(acc[1],  xv.y, rv0);
            ffma2(acc[2],  xv.x, rv1); ffma2(acc[3],  xv.y, rv1);
            ffma2(acc[4],  xv.x, rv2); ffma2(acc[5],  xv.y, rv2);
            ffma2(acc[6],  xv.x, rv3); ffma2(acc[7],  xv.y, rv3);
            ffma2(acc[8],  xv.x, rv4); ffma2(acc[9],  xv.y, rv4);
            ffma2(acc[10], xv.x, rv5); ffma2(acc[11], xv.y, rv5);
            ffma2(acc[12], xv.x, rv6); ffma2(acc[13], xv.y, rv6);
            ffma2(acc[14], xv.x, rv7); ffma2(acc[15], xv.y, rv7);
        }
        __syncthreads();   // phase 2 done reading sX/sR before next staging
    }

    // ---- flush per-block y partials (slab-major, coalesced STG.128)
    float* dst = g_yP + (size_t)blk*BNI;
    #pragma unroll
    for (int j = 0; j < 8; j++){
        float2 p0 = unpack2(acc[2*j]);
        float2 p1 = unpack2(acc[2*j+1]);
        float4 v = {p0.x, p0.y, p1.x, p1.y};
        *(float4*)&dst[(size_t)(b*NN + nb + j)*II + c*4] = v;
    }
}

// ------------------------------------------------ launch (8 kernels)
extern "C" void kernel_launch(void* const* d_in, const int* in_sizes, int n_in,
                              void* d_out, int out_size){
    const float* x = (const float*)d_in[0];
    const float* W = (const float*)d_in[1];
    float* out = (float*)d_out;

    const size_t shmem = (size_t)(TS*II + II*NN + 4*TS*NN) * sizeof(float); // 229376
    cudaFuncSetAttribute(fused_pass_kernel,
                         cudaFuncAttributeMaxDynamicSharedMemorySize, (int)shmem);

    // it 0: r uniform -> nodes0 from xsum
    xsum_kernel<<<dim3(PP, BB), 512>>>(x);
    nodes_update_kernel<<<dim3(NN, 2), 512>>>(W, 1.0f/32.0f, 1, nullptr);

    // it 1
    fused_pass_kernel<<<dim3(NT2, BB), 512, shmem>>>(x, 0);
    reduce_y_kernel<<<256, 256>>>();
    nodes_update_kernel<<<dim3(NN, 2), 512>>>(W, 1.0f, 0, nullptr);

    // it 2
    fused_pass_kernel<<<dim3(NT2, BB), 512, shmem>>>(x, 1);
    reduce_y_kernel<<<256, 256>>>();
    nodes_update_kernel<<<dim3(NN, 2), 512>>>(W, 1.0f, 0, out);
}

// round 15
// speedup vs baseline: 1.3366x; 1.0133x over previous
#include <cuda_runtime.h>

// CapsuleLayer: x[8,2048,512], W[32,512,64] -> nodes[8,32,64]
// Fused routing, capsules never materialized:
//   nodes = (sum_s r*x) @ W[n];  agreement = x . (W[n] @ tanh(nodes))

#define BB 8
#define SS 2048
#define II 512
#define NN 32
#define DD 64
#define TS 64            // s-rows per sub-tile
#define NT2 16           // fused blocks per b (2 sub-tiles each)
#define PP 32            // xsum partial slabs
#define BNI (BB*NN*II)   // 131072

typedef unsigned long long ull;

__device__ __align__(16) float g_xsumP[PP*BB*II];
__device__ __align__(16) float g_yP[NT2*BNI];   // slab-major y partials (8MB)
__device__ __align__(16) float g_y[BNI];        // reduced y (0.5MB)
__device__ __align__(16) float g_U[BB*II*NN];   // [b][i>>2][n][i&3]
__device__ float g_b1[BB*SS*NN];

__device__ __forceinline__ void ffma2(ull &d, ull a, ull b){
    asm("fma.rn.f32x2 %0, %1, %2, %0;" : "+l"(d) : "l"(a), "l"(b));
}
__device__ __forceinline__ ull pack2(float lo, float hi){
    ull r; asm("mov.b64 %0, {%1, %2};" : "=l"(r) : "f"(lo), "f"(hi)); return r;
}
__device__ __forceinline__ float2 unpack2(ull v){
    float2 r; asm("mov.b64 {%0, %1}, %2;" : "=f"(r.x), "=f"(r.y) : "l"(v)); return r;
}

// ------------------------------------------------ xsum partials (no atomics)
// grid (PP,8), 512 thr; 64 rows per slab, MLP 16.
__global__ void xsum_kernel(const float* __restrict__ x){
    int p = blockIdx.x, b = blockIdx.y, tid = threadIdx.x;
    const float* xp = x + ((size_t)(b*SS + p*(SS/PP)))*II + tid;
    float acc = 0.f;
    #pragma unroll 16
    for (int r = 0; r < SS/PP; r++) acc += xp[(size_t)r*II];
    g_xsumP[(size_t)(p*BB + b)*II + tid] = acc;
}

// ------------------------------------------------ yP -> y, single stage
// grid 512 x 256 thr; one float per thread, reduces 16 slabs, MLP 16.
__global__ void reduce_y_kernel(){
    int idx = blockIdx.x*256 + threadIdx.x;      // [0, BNI)
    const float* src = g_yP + idx;
    float a = 0.f;
    #pragma unroll
    for (int t = 0; t < NT2; t++) a += src[(size_t)t*BNI];
    g_y[idx] = a;
}

// ------------------------------------------------ nodes / tanh / U, 4 batches per block
// grid (NN, 2), 512 threads; block = (n, batch-group of 4). One W[n] stream serves 4 b.
__global__ void __launch_bounds__(512)
nodes_update_kernel(const float* __restrict__ W, float scale,
                    int use_xsum, float* __restrict__ out){
    int n = blockIdx.x, bg = blockIdx.y, tid = threadIdx.x;
    __shared__ float ys[4][II];
    __shared__ float sPart[4][32*68];   // padded stride 68
    __shared__ float tsm[4][DD];

    // ---- load ys for 4 batches
    if (tid < II){
        #pragma unroll
        for (int bb = 0; bb < 4; bb++){
            int b = bg*4 + bb;
            float a;
            if (use_xsum){
                a = 0.f;
                const float* p0 = g_xsumP + tid;
                #pragma unroll
                for (int p = 0; p < PP; p++) a += p0[(size_t)(p*BB + b)*II];
            } else {
                a = g_y[(size_t)(b*NN + n)*II + tid];
            }
            ys[bb][tid] = a;
        }
    }
    __syncthreads();

    // ---- part A: nd[b][d] = sum_i ys[b][i]*W[n][i][d]; W quad loaded once per 4 b
    {
        int d4 = tid & 15, ch = tid >> 4;           // 16 d-quads x 32 i-chunks
        const float4* Wp = (const float4*)(W + ((size_t)n*II + ch*16)*DD) + d4;
        float4 a0 = {0,0,0,0}, a1 = {0,0,0,0}, a2 = {0,0,0,0}, a3 = {0,0,0,0};
        #pragma unroll
        for (int j = 0; j < 16; j++){
            float4 w = Wp[j*16];
            float y0 = ys[0][ch*16+j], y1 = ys[1][ch*16+j];
            float y2 = ys[2][ch*16+j], y3 = ys[3][ch*16+j];
            a0.x += y0*w.x; a0.y += y0*w.y; a0.z += y0*w.z; a0.w += y0*w.w;
            a1.x += y1*w.x; a1.y += y1*w.y; a1.z += y1*w.z; a1.w += y1*w.w;
            a2.x += y2*w.x; a2.y += y2*w.y; a2.z += y2*w.z; a2.w += y2*w.w;
            a3.x += y3*w.x; a3.y += y3*w.y; a3.z += y3*w.z; a3.w += y3*w.w;
        }
        float* s0 = &sPart[0][ch*68 + d4*4];
        float* s1 = &sPart[1][ch*68 + d4*4];
        float* s2 = &sPart[2][ch*68 + d4*4];
        float* s3 = &sPart[3][ch*68 + d4*4];
        s0[0]=a0.x; s0[1]=a0.y; s0[2]=a0.z; s0[3]=a0.w;
        s1[0]=a1.x; s1[1]=a1.y; s1[2]=a1.z; s1[3]=a1.w;
        s2[0]=a2.x; s2[1]=a2.y; s2[2]=a2.z; s2[3]=a2.w;
        s3[0]=a3.x; s3[1]=a3.y; s3[2]=a3.z; s3[3]=a3.w;
    }
    __syncthreads();
    if (tid < 256){
        int bb = tid >> 6, d = tid & 63;
        float nd = 0.f;
        #pragma unroll
        for (int ch = 0; ch < 32; ch++) nd += sPart[bb][ch*68 + d];
        nd *= scale;
        if (out) out[(size_t)((bg*4+bb)*NN + n)*DD + d] = nd;
        else     tsm[bb][d] = tanhf(nd);
    }
    __syncthreads();

    // ---- part B: U[b,n,i] = W[n][i][:] . tanh(nd[b]); one i per thread, 4 b per W row
    if (!out){
        int i = tid;
        const float4* Wr = (const float4*)(W + ((size_t)n*II + i)*DD);
        float u0 = 0.f, u1 = 0.f, u2 = 0.f, u3 = 0.f;
        #pragma unroll
        for (int d4 = 0; d4 < 16; d4++){
            float4 w = Wr[d4];
            u0 += w.x*tsm[0][4*d4] + w.y*tsm[0][4*d4+1] + w.z*tsm[0][4*d4+2] + w.w*tsm[0][4*d4+3];
            u1 += w.x*tsm[1][4*d4] + w.y*tsm[1][4*d4+1] + w.z*tsm[1][4*d4+2] + w.w*tsm[1][4*d4+3];
            u2 += w.x*tsm[2][4*d4] + w.y*tsm[2][4*d4+1] + w.z*tsm[2][4*d4+2] + w.w*tsm[2][4*d4+3];
            u3 += w.x*tsm[3][4*d4] + w.y*tsm[3][4*d4+1] + w.z*tsm[3][4*d4+2] + w.w*tsm[3][4*d4+3];
        }
        size_t off = (size_t)(i>>2)*(NN*4) + n*4 + (i&3);
        g_U[(size_t)(bg*4+0)*(II*NN) + off] = u0;
        g_U[(size_t)(bg*4+1)*(II*NN) + off] = u1;
        g_U[(size_t)(bg*4+2)*(II*NN) + off] = u2;
        g_U[(size_t)(bg*4+3)*(II*NN) + off] = u3;
    }
}

// ------------------------------------------------ fused routing pass (2 sub-tiles/block)
// a[n] = x.U[n] (+b_prev) -> softmax_n -> acc += r^T x; flush once to yP[blk].
// grid (NT2, BB), 512 threads, 224KB dynamic smem.
__global__ void __launch_bounds__(512, 1)
fused_pass_kernel(const float* __restrict__ x, int pass_c){
    extern __shared__ float smem[];
    float* sX = smem;             // TS*II  = 32768 floats (128KB)
    float* sU = sX + TS*II;       // II*NN  = 16384 floats (64KB, quad layout)
    float* sP = sU + II*NN;       // 4*TS*NN = 8192 floats (32KB, K-split partials)
    float* sR = sP;               // aliases sP (guarded by barriers)
    int blk = blockIdx.x, b = blockIdx.y, tid = threadIdx.x;
    int warp = tid >> 5, lane = tid & 31;

    // ---- stage U once
    const float* Ub = g_U + (size_t)b*(II*NN);
    #pragma unroll
    for (int it = 0; it < II*NN/4/512; it++)
        ((float4*)sU)[it*512 + tid] = ((const float4*)Ub)[it*512 + tid];

    // phase-2 persistent accumulators: thread -> 8 n x 4 i-floats
    int g2 = tid >> 7, c = tid & 127, nb = g2*8;
    ull acc[16];
    #pragma unroll
    for (int p = 0; p < 16; p++) acc[p] = 0ULL;

    #pragma unroll 1
    for (int st = 0; st < 2; st++){
        int s0 = (blk*2 + st)*TS;

        // ---- stage x sub-tile (coalesced float4)
        const float* xt = x + ((size_t)(b*SS + s0))*II;
        #pragma unroll
        for (int it = 0; it < TS*II/4/512; it++)
            ((float4*)sX)[it*512 + tid] = ((const float4*)xt)[it*512 + tid];
        __syncthreads();

        // ---- phase 1a: agreement; warp = (rg rows of 16, ks K-slice of 32 quads)
        {
            int rg = warp >> 2, ks = warp & 3;
            int row0 = rg*16, q0 = ks*32;
            ull a2[16];
            #pragma unroll
            for (int r = 0; r < 16; r++) a2[r] = 0ULL;
            const ulonglong2* U2 = (const ulonglong2*)sU;   // [q*NN + n] -> 4 floats
            #pragma unroll 2
            for (int qq = 0; qq < 32; qq++){
                int q = q0 + qq;
                ulonglong2 u = U2[q*NN + lane];
                #pragma unroll
                for (int rr = 0; rr < 16; rr++){
                    const ulonglong2 xv = *(const ulonglong2*)&sX[(row0+rr)*II + q*4];
                    ffma2(a2[rr], xv.x, u.x);
                    ffma2(a2[rr], xv.y, u.y);
                }
            }
            #pragma unroll
            for (int rr = 0; rr < 16; rr++){
                float2 p = unpack2(a2[rr]);
                sP[ks*(TS*NN) + (row0+rr)*NN + lane] = p.x + p.y;
            }
        }
        __syncthreads();

        // ---- phase 1b: combine 4 K-splits + softmax; each warp 4 rows, lane = n
        {
            int row0 = warp*4;
            float rv[4];
            #pragma unroll
            for (int rr = 0; rr < 4; rr++){
                int row = row0 + rr;
                float a = sP[row*NN + lane]
                        + sP[TS*NN + row*NN + lane]
                        + sP[2*TS*NN + row*NN + lane]
                        + sP[3*TS*NN + row*NN + lane];
                int gidx = ((b*SS) + s0 + row)*NN + lane;
                if (pass_c) a += g_b1[gidx];
                else        g_b1[gidx] = a;
                float m = a;
                #pragma unroll
                for (int off = 16; off > 0; off >>= 1)
                    m = fmaxf(m, __shfl_xor_sync(0xffffffffu, m, off));
                float e = __expf(a - m);
                float ssum = e;
                #pragma unroll
                for (int off = 16; off > 0; off >>= 1)
                    ssum += __shfl_xor_sync(0xffffffffu, ssum, off);
                rv[rr] = e / ssum;
            }
            __syncthreads();             // all sP reads done before aliasing writes
            #pragma unroll
            for (int rr = 0; rr < 4; rr++)
                sR[(row0+rr)*NN + lane] = rv[rr];
        }
        __syncthreads();

        // ---- phase 2: acc += r^T x over this sub-tile
        for (int ts = 0; ts < TS; ts++){
            const ulonglong2 rA = *(const ulonglong2*)&sR[ts*NN + nb];
            const ulonglong2 rB = *(const ulonglong2*)&sR[ts*NN + nb + 4];
            float2 r01 = unpack2(rA.x), r23 = unpack2(rA.y);
            float2 r45 = unpack2(rB.x), r67 = unpack2(rB.y);
            ull rv0 = pack2(r01.x, r01.x), rv1 = pack2(r01.y, r01.y);
            ull rv2 = pack2(r23.x, r23.x), rv3 = pack2(r23.y, r23.y);
            ull rv4 = pack2(r45.x, r45.x), rv5 = pack2(r45.y, r45.y);
            ull rv6 = pack2(r67.x, r67.x), rv7 = pack2(r67.y, r67.y);
            const ulonglong2 xv = *(const ulonglong2*)&sX[ts*II + c*4];
            ffma2(acc[0],  xv.x, rv0); ffma2(acc[1],  xv.y, rv0);
            ffma2(acc[2],  xv.x, rv1); ffma2(acc[3],  xv.y, rv1);
            ffma2(acc[4],  xv.x, rv2); ffma2(acc[5],  xv.y, rv2);
            ffma2(acc[6],  xv.x, rv3); ffma2(acc[7],  xv.y, rv3);
            ffma2(acc[8],  xv.x, rv4); ffma2(acc[9],  xv.y, rv4);
            ffma2(acc[10], xv.x, rv5); ffma2(acc[11], xv.y, rv5);
            ffma2(acc[12], xv.x, rv6); ffma2(acc[13], xv.y, rv6);
            ffma2(acc[14], xv.x, rv7); ffma2(acc[15], xv.y, rv7);
        }
        __syncthreads();   // phase 2 done reading sX/sR before next staging
    }

    // ---- flush per-block y partials (slab-major, coalesced STG.128)
    float* dst = g_yP + (size_t)blk*BNI;
    #pragma unroll
    for (int j = 0; j < 8; j++){
        float2 p0 = unpack2(acc[2*j]);
        float2 p1 = unpack2(acc[2*j+1]);
        float4 v = {p0.x, p0.y, p1.x, p1.y};
        *(float4*)&dst[(size_t)(b*NN + nb + j)*II + c*4] = v;
    }
}

// ------------------------------------------------ launch (8 kernels)
extern "C" void kernel_launch(void* const* d_in, const int* in_sizes, int n_in,
                              void* d_out, int out_size){
    const float* x = (const float*)d_in[0];
    const float* W = (const float*)d_in[1];
    float* out = (float*)d_out;

    const size_t shmem = (size_t)(TS*II + II*NN + 4*TS*NN) * sizeof(float); // 229376
    cudaFuncSetAttribute(fused_pass_kernel,
                         cudaFuncAttributeMaxDynamicSharedMemorySize, (int)shmem);

    // it 0: r uniform -> nodes0 from xsum
    xsum_kernel<<<dim3(PP, BB), 512>>>(x);
    nodes_update_kernel<<<dim3(NN, 2), 512>>>(W, 1.0f/32.0f, 1, nullptr);

    // it 1
    fused_pass_kernel<<<dim3(NT2, BB), 512, shmem>>>(x, 0);
    reduce_y_kernel<<<512, 256>>>();
    nodes_update_kernel<<<dim3(NN, 2), 512>>>(W, 1.0f, 0, nullptr);

    // it 2
    fused_pass_kernel<<<dim3(NT2, BB), 512, shmem>>>(x, 1);
    reduce_y_kernel<<<512, 256>>>();
    nodes_update_kernel<<<dim3(NN, 2), 512>>>(W, 1.0f, 0, out);
}

// round 16
// speedup vs baseline: 1.3669x; 1.0227x over previous
#include <cuda_runtime.h>

// CapsuleLayer: x[8,2048,512], W[32,512,64] -> nodes[8,32,64]
// Fused routing, capsules never materialized:
//   nodes = (sum_s r*x) @ W[n];  agreement = x . (W[n] @ tanh(nodes))

#define BB 8
#define SS 2048
#define II 512
#define NN 32
#define DD 64
#define TS 64            // s-rows per sub-tile
#define NT2 16           // fused blocks per b (2 sub-tiles each)
#define PP 32            // xsum partial slabs
#define BNI (BB*NN*II)   // 131072

typedef unsigned long long ull;

__device__ __align__(16) float g_xsumP[PP*BB*II];
__device__ __align__(16) float g_yP[NT2*BNI];   // slab-major y partials (8MB)
__device__ __align__(16) float g_U[BB*II*NN];   // [b][i>>2][n][i&3]
__device__ float g_b1[BB*SS*NN];

__device__ __forceinline__ void ffma2(ull &d, ull a, ull b){
    asm("fma.rn.f32x2 %0, %1, %2, %0;" : "+l"(d) : "l"(a), "l"(b));
}
__device__ __forceinline__ ull pack2(float lo, float hi){
    ull r; asm("mov.b64 %0, {%1, %2};" : "=l"(r) : "f"(lo), "f"(hi)); return r;
}
__device__ __forceinline__ float2 unpack2(ull v){
    float2 r; asm("mov.b64 {%0, %1}, %2;" : "=f"(r.x), "=f"(r.y) : "l"(v)); return r;
}

// ------------------------------------------------ xsum partials (no atomics)
// grid (PP,8), 512 thr; 64 rows per slab, MLP 16.
__global__ void xsum_kernel(const float* __restrict__ x){
    int p = blockIdx.x, b = blockIdx.y, tid = threadIdx.x;
    const float* xp = x + ((size_t)(b*SS + p*(SS/PP)))*II + tid;
    float acc = 0.f;
    #pragma unroll 16
    for (int r = 0; r < SS/PP; r++) acc += xp[(size_t)r*II];
    g_xsumP[(size_t)(p*BB + b)*II + tid] = acc;
}

// ------------------------------------------------ nodes / tanh / U, 4 batches per block
// grid (NN, 2), 512 threads; block = (n, batch-group of 4). One W[n] stream serves 4 b.
// ys load now reduces the 16 yP slabs in-kernel (64 independent loads/thread).
__global__ void __launch_bounds__(512)
nodes_update_kernel(const float* __restrict__ W, float scale,
                    int use_xsum, float* __restrict__ out){
    int n = blockIdx.x, bg = blockIdx.y, tid = threadIdx.x;
    __shared__ float ys[4][II];
    __shared__ float sPart[4][32*68];   // padded stride 68
    __shared__ float tsm[4][DD];

    // ---- load ys for 4 batches (xsum partials OR 16-deep yP reduction)
    if (tid < II){
        if (use_xsum){
            #pragma unroll
            for (int bb = 0; bb < 4; bb++){
                int b = bg*4 + bb;
                float a = 0.f;
                const float* p0 = g_xsumP + tid;
                #pragma unroll
                for (int p = 0; p < PP; p++) a += p0[(size_t)(p*BB + b)*II];
                ys[bb][tid] = a;
            }
        } else {
            float a0 = 0.f, a1 = 0.f, a2 = 0.f, a3 = 0.f;
            const float* p0 = g_yP + (size_t)((bg*4+0)*NN + n)*II + tid;
            const float* p1 = g_yP + (size_t)((bg*4+1)*NN + n)*II + tid;
            const float* p2 = g_yP + (size_t)((bg*4+2)*NN + n)*II + tid;
            const float* p3 = g_yP + (size_t)((bg*4+3)*NN + n)*II + tid;
            #pragma unroll
            for (int t = 0; t < NT2; t++){
                size_t off = (size_t)t*BNI;
                a0 += p0[off]; a1 += p1[off]; a2 += p2[off]; a3 += p3[off];
            }
            ys[0][tid] = a0; ys[1][tid] = a1; ys[2][tid] = a2; ys[3][tid] = a3;
        }
    }
    __syncthreads();

    // ---- part A: nd[b][d] = sum_i ys[b][i]*W[n][i][d]; W quad loaded once per 4 b
    {
        int d4 = tid & 15, ch = tid >> 4;           // 16 d-quads x 32 i-chunks
        const float4* Wp = (const float4*)(W + ((size_t)n*II + ch*16)*DD) + d4;
        float4 a0 = {0,0,0,0}, a1 = {0,0,0,0}, a2 = {0,0,0,0}, a3 = {0,0,0,0};
        #pragma unroll
        for (int j = 0; j < 16; j++){
            float4 w = Wp[j*16];
            float y0 = ys[0][ch*16+j], y1 = ys[1][ch*16+j];
            float y2 = ys[2][ch*16+j], y3 = ys[3][ch*16+j];
            a0.x += y0*w.x; a0.y += y0*w.y; a0.z += y0*w.z; a0.w += y0*w.w;
            a1.x += y1*w.x; a1.y += y1*w.y; a1.z += y1*w.z; a1.w += y1*w.w;
            a2.x += y2*w.x; a2.y += y2*w.y; a2.z += y2*w.z; a2.w += y2*w.w;
            a3.x += y3*w.x; a3.y += y3*w.y; a3.z += y3*w.z; a3.w += y3*w.w;
        }
        float* s0 = &sPart[0][ch*68 + d4*4];
        float* s1 = &sPart[1][ch*68 + d4*4];
        float* s2 = &sPart[2][ch*68 + d4*4];
        float* s3 = &sPart[3][ch*68 + d4*4];
        s0[0]=a0.x; s0[1]=a0.y; s0[2]=a0.z; s0[3]=a0.w;
        s1[0]=a1.x; s1[1]=a1.y; s1[2]=a1.z; s1[3]=a1.w;
        s2[0]=a2.x; s2[1]=a2.y; s2[2]=a2.z; s2[3]=a2.w;
        s3[0]=a3.x; s3[1]=a3.y; s3[2]=a3.z; s3[3]=a3.w;
    }
    __syncthreads();
    if (tid < 256){
        int bb = tid >> 6, d = tid & 63;
        float nd = 0.f;
        #pragma unroll
        for (int ch = 0; ch < 32; ch++) nd += sPart[bb][ch*68 + d];
        nd *= scale;
        if (out) out[(size_t)((bg*4+bb)*NN + n)*DD + d] = nd;
        else     tsm[bb][d] = tanhf(nd);
    }
    __syncthreads();

    // ---- part B: U[b,n,i] = W[n][i][:] . tanh(nd[b]); one i per thread, 4 b per W row
    if (!out){
        int i = tid;
        const float4* Wr = (const float4*)(W + ((size_t)n*II + i)*DD);
        float u0 = 0.f, u1 = 0.f, u2 = 0.f, u3 = 0.f;
        #pragma unroll
        for (int d4 = 0; d4 < 16; d4++){
            float4 w = Wr[d4];
            u0 += w.x*tsm[0][4*d4] + w.y*tsm[0][4*d4+1] + w.z*tsm[0][4*d4+2] + w.w*tsm[0][4*d4+3];
            u1 += w.x*tsm[1][4*d4] + w.y*tsm[1][4*d4+1] + w.z*tsm[1][4*d4+2] + w.w*tsm[1][4*d4+3];
            u2 += w.x*tsm[2][4*d4] + w.y*tsm[2][4*d4+1] + w.z*tsm[2][4*d4+2] + w.w*tsm[2][4*d4+3];
            u3 += w.x*tsm[3][4*d4] + w.y*tsm[3][4*d4+1] + w.z*tsm[3][4*d4+2] + w.w*tsm[3][4*d4+3];
        }
        size_t off = (size_t)(i>>2)*(NN*4) + n*4 + (i&3);
        g_U[(size_t)(bg*4+0)*(II*NN) + off] = u0;
        g_U[(size_t)(bg*4+1)*(II*NN) + off] = u1;
        g_U[(size_t)(bg*4+2)*(II*NN) + off] = u2;
        g_U[(size_t)(bg*4+3)*(II*NN) + off] = u3;
    }
}

// ------------------------------------------------ fused routing pass (2 sub-tiles/block)
// a[n] = x.U[n] (+b_prev) -> softmax_n -> acc += r^T x; flush once to yP[blk].
// grid (NT2, BB), 512 threads, 224KB dynamic smem.
__global__ void __launch_bounds__(512, 1)
fused_pass_kernel(const float* __restrict__ x, int pass_c){
    extern __shared__ float smem[];
    float* sX = smem;             // TS*II  = 32768 floats (128KB)
    float* sU = sX + TS*II;       // II*NN  = 16384 floats (64KB, quad layout)
    float* sP = sU + II*NN;       // 4*TS*NN = 8192 floats (32KB, K-split partials)
    float* sR = sP;               // aliases sP (guarded by barriers)
    int blk = blockIdx.x, b = blockIdx.y, tid = threadIdx.x;
    int warp = tid >> 5, lane = tid & 31;

    // ---- stage U once
    const float* Ub = g_U + (size_t)b*(II*NN);
    #pragma unroll
    for (int it = 0; it < II*NN/4/512; it++)
        ((float4*)sU)[it*512 + tid] = ((const float4*)Ub)[it*512 + tid];

    // phase-2 persistent accumulators: thread -> 8 n x 4 i-floats
    int g2 = tid >> 7, c = tid & 127, nb = g2*8;
    ull acc[16];
    #pragma unroll
    for (int p = 0; p < 16; p++) acc[p] = 0ULL;

    #pragma unroll 1
    for (int st = 0; st < 2; st++){
        int s0 = (blk*2 + st)*TS;

        // ---- stage x sub-tile (coalesced float4)
        const float* xt = x + ((size_t)(b*SS + s0))*II;
        #pragma unroll
        for (int it = 0; it < TS*II/4/512; it++)
            ((float4*)sX)[it*512 + tid] = ((const float4*)xt)[it*512 + tid];
        __syncthreads();

        // ---- phase 1a: agreement; warp = (rg rows of 16, ks K-slice of 32 quads)
        {
            int rg = warp >> 2, ks = warp & 3;
            int row0 = rg*16, q0 = ks*32;
            ull a2[16];
            #pragma unroll
            for (int r = 0; r < 16; r++) a2[r] = 0ULL;
            const ulonglong2* U2 = (const ulonglong2*)sU;   // [q*NN + n] -> 4 floats
            #pragma unroll 2
            for (int qq = 0; qq < 32; qq++){
                int q = q0 + qq;
                ulonglong2 u = U2[q*NN + lane];
                #pragma unroll
                for (int rr = 0; rr < 16; rr++){
                    const ulonglong2 xv = *(const ulonglong2*)&sX[(row0+rr)*II + q*4];
                    ffma2(a2[rr], xv.x, u.x);
                    ffma2(a2[rr], xv.y, u.y);
                }
            }
            #pragma unroll
            for (int rr = 0; rr < 16; rr++){
                float2 p = unpack2(a2[rr]);
                sP[ks*(TS*NN) + (row0+rr)*NN + lane] = p.x + p.y;
            }
        }
        __syncthreads();

        // ---- phase 1b: combine 4 K-splits + softmax; each warp 4 rows, lane = n
        {
            int row0 = warp*4;
            float rv[4];
            #pragma unroll
            for (int rr = 0; rr < 4; rr++){
                int row = row0 + rr;
                float a = sP[row*NN + lane]
                        + sP[TS*NN + row*NN + lane]
                        + sP[2*TS*NN + row*NN + lane]
                        + sP[3*TS*NN + row*NN + lane];
                int gidx = ((b*SS) + s0 + row)*NN + lane;
                if (pass_c) a += g_b1[gidx];
                else        g_b1[gidx] = a;
                float m = a;
                #pragma unroll
                for (int off = 16; off > 0; off >>= 1)
                    m = fmaxf(m, __shfl_xor_sync(0xffffffffu, m, off));
                float e = __expf(a - m);
                float ssum = e;
                #pragma unroll
                for (int off = 16; off > 0; off >>= 1)
                    ssum += __shfl_xor_sync(0xffffffffu, ssum, off);
                rv[rr] = e / ssum;
            }
            __syncthreads();             // all sP reads done before aliasing writes
            #pragma unroll
            for (int rr = 0; rr < 4; rr++)
                sR[(row0+rr)*NN + lane] = rv[rr];
        }
        __syncthreads();

        // ---- phase 2: acc += r^T x over this sub-tile
        for (int ts = 0; ts < TS; ts++){
            const ulonglong2 rA = *(const ulonglong2*)&sR[ts*NN + nb];
            const ulonglong2 rB = *(const ulonglong2*)&sR[ts*NN + nb + 4];
            float2 r01 = unpack2(rA.x), r23 = unpack2(rA.y);
            float2 r45 = unpack2(rB.x), r67 = unpack2(rB.y);
            ull rv0 = pack2(r01.x, r01.x), rv1 = pack2(r01.y, r01.y);
            ull rv2 = pack2(r23.x, r23.x), rv3 = pack2(r23.y, r23.y);
            ull rv4 = pack2(r45.x, r45.x), rv5 = pack2(r45.y, r45.y);
            ull rv6 = pack2(r67.x, r67.x), rv7 = pack2(r67.y, r67.y);
            const ulonglong2 xv = *(const ulonglong2*)&sX[ts*II + c*4];
            ffma2(acc[0],  xv.x, rv0); ffma2(acc[1],  xv.y, rv0);
            ffma2(acc[2],  xv.x, rv1); ffma2(acc[3],  xv.y, rv1);
            ffma2(acc[4],  xv.x, rv2); ffma2(acc[5],  xv.y, rv2);
            ffma2(acc[6],  xv.x, rv3); ffma2(acc[7],  xv.y, rv3);
            ffma2(acc[8],  xv.x, rv4); ffma2(acc[9],  xv.y, rv4);
            ffma2(acc[10], xv.x, rv5); ffma2(acc[11], xv.y, rv5);
            ffma2(acc[12], xv.x, rv6); ffma2(acc[13], xv.y, rv6);
            ffma2(acc[14], xv.x, rv7); ffma2(acc[15], xv.y, rv7);
        }
        __syncthreads();   // phase 2 done reading sX/sR before next staging
    }

    // ---- flush per-block y partials (slab-major, coalesced STG.128)
    float* dst = g_yP + (size_t)blk*BNI;
    #pragma unroll
    for (int j = 0; j < 8; j++){
        float2 p0 = unpack2(acc[2*j]);
        float2 p1 = unpack2(acc[2*j+1]);
        float4 v = {p0.x, p0.y, p1.x, p1.y};
        *(float4*)&dst[(size_t)(b*NN + nb + j)*II + c*4] = v;
    }
}

// ------------------------------------------------ launch (6 kernels)
extern "C" void kernel_launch(void* const* d_in, const int* in_sizes, int n_in,
                              void* d_out, int out_size){
    const float* x = (const float*)d_in[0];
    const float* W = (const float*)d_in[1];
    float* out = (float*)d_out;

    const size_t shmem = (size_t)(TS*II + II*NN + 4*TS*NN) * sizeof(float); // 229376
    cudaFuncSetAttribute(fused_pass_kernel,
                         cudaFuncAttributeMaxDynamicSharedMemorySize, (int)shmem);

    // it 0: r uniform -> nodes0 from xsum
    xsum_kernel<<<dim3(PP, BB), 512>>>(x);
    nodes_update_kernel<<<dim3(NN, 2), 512>>>(W, 1.0f/32.0f, 1, nullptr);

    // it 1
    fused_pass_kernel<<<dim3(NT2, BB), 512, shmem>>>(x, 0);
    nodes_update_kernel<<<dim3(NN, 2), 512>>>(W, 1.0f, 0, nullptr);

    // it 2
    fused_pass_kernel<<<dim3(NT2, BB), 512, shmem>>>(x, 1);
    nodes_update_kernel<<<dim3(NN, 2), 512>>>(W, 1.0f, 0, out);
}